// round 11
// baseline (speedup 1.0000x reference)
#include <cuda_runtime.h>
#include <cuda_bf16.h>

#define FULL_MASK 0xffffffffu
#define EPW 128          // edges per warp-chunk (4 groups x 32 edges)
#define D   32           // feature dim (fixed by problem shape)

// Boundary tables: for every NON-EMPTY segment s, g_pos[s] = first edge index,
// g_end[s] = one-past-last edge index. Empty segments keep stale entries —
// deterministic (same inputs each replay; zero-initialized at load) and
// harmless (their sums are 0; inv stays finite). No reset needed.
__device__ int g_pos[1 << 20];   // supports N up to 1M
__device__ int g_end[1 << 20];

// ---------------------------------------------------------------------------
// Kernel 1: branch-light boundary marking on sorted sid (scan ONLY).
// Thread i owns edges [4i, 4i+4): one int4 load + one peek. Each boundary
// sid[e] != sid[e+1] emits exactly two stores. Head/tail handled by thread 0
// and the thread owning edge E-1. No loops, no other duties.
// ---------------------------------------------------------------------------
__global__ void __launch_bounds__(256)
k_mark(const int* __restrict__ sid, int E)
{
    const int i  = blockIdx.x * blockDim.x + threadIdx.x;
    const int e0 = i * 4;
    if (e0 >= E) return;

    int a[5];
    if (e0 + 4 <= E) {
        int4 v = __ldg((const int4*)sid + i);
        a[0] = v.x; a[1] = v.y; a[2] = v.z; a[3] = v.w;
    } else {
        a[0] = __ldg(sid + e0);
        a[1] = (e0 + 1 < E) ? __ldg(sid + e0 + 1) : a[0];
        a[2] = (e0 + 2 < E) ? __ldg(sid + e0 + 2) : a[1];
        a[3] = (e0 + 3 < E) ? __ldg(sid + e0 + 3) : a[2];
    }
    a[4] = (e0 + 4 < E) ? __ldg(sid + e0 + 4) : a[3];

    if (i == 0) g_pos[a[0]] = 0;

    #pragma unroll
    for (int j = 0; j < 4; ++j) {
        const int e = e0 + j;
        if (e + 1 < E) {
            const int cur = a[j], ns = a[j + 1];
            if (ns != cur) { g_end[cur] = e + 1; g_pos[ns] = e + 1; }
        } else if (e + 1 == E) {
            g_end[a[j]] = E;
        }
    }
}

// ---------------------------------------------------------------------------
// 128-bit reduction (fire-and-forget) — sm_90+ vector atomic
// ---------------------------------------------------------------------------
__device__ __forceinline__ void red_add_v4(float4* p, float4 s) {
    asm volatile("red.global.add.v4.f32 [%0], {%1, %2, %3, %4};"
                 :: "l"(p), "f"(s.x), "f"(s.y), "f"(s.z), "f"(s.w)
                 : "memory");
}

__device__ __forceinline__ void flush_seg(float4* __restrict__ out4, int seg,
                                          float4 s, int sub) {
    red_add_v4(&out4[(long long)seg * 8 + sub], s);
}

// ---------------------------------------------------------------------------
// Kernel 2: gather + sorted-segment raw sum (round-10 engine, VERBATIM).
// Warp = 4 groups of 8 lanes. Group g owns contiguous edges
// [start + g*32, start + g*32 + 32). Lane sub owns feature columns
// [sub*4, sub*4+4) as a float4. Phase 1 issues 8 independent LDG.128 row
// reads (MLP=8/lane); phase 2 run-length accumulates, flushing raw sums
// with ONE REDG.128 per lane on segment change. Nothing else inside.
// ---------------------------------------------------------------------------
__global__ void __launch_bounds__(256)
k_agg(const float* __restrict__ src,
      const int*   __restrict__ gidx,
      const int*   __restrict__ sid,
      float4*      __restrict__ out4,
      int E)
{
    const int lane = threadIdx.x & 31;
    const int sub  = lane & 7;
    const long long warp  = ((long long)blockIdx.x * blockDim.x + threadIdx.x) >> 5;
    const long long start = warp * (long long)EPW;
    if (start >= E) return;

    if (start + EPW <= E) {
        // ---------- fast path: full 128-edge chunk ----------
        int4 gi4 = __ldg((const int4*)(gidx + start) + lane);
        int4 si4 = __ldg((const int4*)(sid  + start) + lane);
        int gi[4] = {gi4.x, gi4.y, gi4.z, gi4.w};
        int si[4] = {si4.x, si4.y, si4.z, si4.w};

        int    cur = -1;
        float4 sum = make_float4(0.f, 0.f, 0.f, 0.f);

        #pragma unroll
        for (int jo = 0; jo < 32; jo += 8) {
            float4 val[8];
            #pragma unroll
            for (int jj = 0; jj < 8; ++jj) {
                const int j = jo + jj;
                int idx = __shfl_sync(FULL_MASK, gi[j & 3], j >> 2, 8);
                val[jj] = __ldg((const float4*)(src + (long long)idx * D) + sub);
            }
            #pragma unroll
            for (int jj = 0; jj < 8; ++jj) {
                const int j = jo + jj;
                int seg = __shfl_sync(FULL_MASK, si[j & 3], j >> 2, 8);
                if (seg != cur) {
                    if (cur >= 0) flush_seg(out4, cur, sum, sub);
                    cur = seg; sum = make_float4(0.f, 0.f, 0.f, 0.f);
                }
                sum.x += val[jj].x; sum.y += val[jj].y;
                sum.z += val[jj].z; sum.w += val[jj].w;
            }
        }
        flush_seg(out4, cur, sum, sub);
    } else {
        // ---------- tail path: partial chunk, per-group scalar loop ----------
        const int group = lane >> 3;
        long long gstart = start + (long long)group * 32;
        long long gend   = min(gstart + 32, (long long)E);

        int    cur = -1;
        float4 sum = make_float4(0.f, 0.f, 0.f, 0.f);

        for (long long e = gstart; e < gend; ++e) {
            int idx = __ldg(gidx + e);
            int seg = __ldg(sid  + e);
            float4 v = __ldg((const float4*)(src + (long long)idx * D) + sub);
            if (seg != cur) {
                if (cur >= 0) flush_seg(out4, cur, sum, sub);
                cur = seg; sum = make_float4(0.f, 0.f, 0.f, 0.f);
            }
            sum.x += v.x; sum.y += v.y; sum.z += v.z; sum.w += v.w;
        }
        if (cur >= 0) flush_seg(out4, cur, sum, sub);
    }
}

// ---------------------------------------------------------------------------
// Kernel 3: out[n][:] *= 1/max(g_end[n]-g_pos[n], 1)   (streaming, 26 MB)
// Stale entries for empty segments give a finite inv; sum is 0 -> out 0.
// ---------------------------------------------------------------------------
__global__ void k_fin(float4* __restrict__ out4, int nq) {
    int i = blockIdx.x * blockDim.x + threadIdx.x;
    if (i >= nq) return;
    const int n = i >> 3;
    const int s = __ldg(g_pos + n);
    const int t = __ldg(g_end + n);
    const float inv = 1.0f / (float)max(t - s, 1);
    float4 v = out4[i];
    v.x *= inv; v.y *= inv; v.z *= inv; v.w *= inv;
    out4[i] = v;
}

// ---------------------------------------------------------------------------
extern "C" void kernel_launch(void* const* d_in, const int* in_sizes, int n_in,
                              void* d_out, int out_size)
{
    const float* src  = (const float*)d_in[0];   // [N, 32] f32
    const int*   gidx = (const int*)  d_in[1];   // [E] i32
    const int*   sid  = (const int*)  d_in[2];   // [E] i32 (sorted)
    float4*      out4 = (float4*)d_out;          // [N, 32] f32

    const int E  = in_sizes[1];
    const int nq = out_size / 4;

    // 0) zero the output via a graph memset node (driver-optimized, ~DRAM BW)
    cudaMemsetAsync(d_out, 0, (size_t)out_size * sizeof(float), 0);

    // 1) boundary marks (scan only)
    {
        int threads_needed = (E + 3) / 4;
        int blocks = (threads_needed + 255) / 256;
        k_mark<<<blocks, 256>>>(sid, E);
    }
    // 2) gather + raw segment sums (REDG.128 flush)
    {
        long long warps  = ((long long)E + EPW - 1) / EPW;
        long long tcount = warps * 32;
        int blocks = (int)((tcount + 255) / 256);
        k_agg<<<blocks, 256>>>(src, gidx, sid, out4, E);
    }
    // 3) scale by 1/count
    {
        int blocks = (nq + 255) / 256;
        k_fin<<<blocks, 256>>>(out4, nq);
    }
}

// round 12
// speedup vs baseline: 1.0548x; 1.0548x over previous
#include <cuda_runtime.h>
#include <cuda_bf16.h>

#define FULL_MASK 0xffffffffu
#define EPW 128          // edges per warp-chunk (4 groups x 32 edges)
#define D   32           // feature dim (fixed by problem shape)

// Per-segment edge counts. Zero-initialized at module load; k_fin re-zeros
// after consuming, so every kernel_launch call (correctness run + each graph
// replay) sees zeros. No allocation, no static guards.
__device__ float g_counts[1 << 20];   // 4 MB, supports N up to 1M

// ---------------------------------------------------------------------------
// 128-bit reduction (fire-and-forget) — sm_90+ vector atomic
// ---------------------------------------------------------------------------
__device__ __forceinline__ void red_add_v4(float4* p, float4 s) {
    asm volatile("red.global.add.v4.f32 [%0], {%1, %2, %3, %4};"
                 :: "l"(p), "f"(s.x), "f"(s.y), "f"(s.z), "f"(s.w)
                 : "memory");
}

// flush: one REDG.128 for the run's raw sum; group leader (sub==0) also
// flushes the run's edge count.
__device__ __forceinline__ void flush_seg(float4* __restrict__ out4, int seg,
                                          float4 s, int cnt, int sub) {
    red_add_v4(&out4[(long long)seg * 8 + sub], s);
    if (sub == 0) atomicAdd(&g_counts[seg], (float)cnt);
}

// ---------------------------------------------------------------------------
// Kernel 1: gather + sorted-segment raw sum + counts (round-10 engine + cnt).
// Warp = 4 groups of 8 lanes. Group g owns contiguous edges
// [start + g*32, start + g*32 + 32). Lane sub owns feature columns
// [sub*4, sub*4+4) as a float4. Phase 1 issues 8 independent LDG.128 row
// reads (MLP=8/lane); phase 2 run-length accumulates, flushing on segment
// change with one REDG.128 per lane + one count REDG per group.
// ---------------------------------------------------------------------------
__global__ void __launch_bounds__(256)
k_agg(const float* __restrict__ src,
      const int*   __restrict__ gidx,
      const int*   __restrict__ sid,
      float4*      __restrict__ out4,
      int E)
{
    const int lane = threadIdx.x & 31;
    const int sub  = lane & 7;
    const long long warp  = ((long long)blockIdx.x * blockDim.x + threadIdx.x) >> 5;
    const long long start = warp * (long long)EPW;
    if (start >= E) return;

    if (start + EPW <= E) {
        // ---------- fast path: full 128-edge chunk ----------
        int4 gi4 = __ldg((const int4*)(gidx + start) + lane);
        int4 si4 = __ldg((const int4*)(sid  + start) + lane);
        int gi[4] = {gi4.x, gi4.y, gi4.z, gi4.w};
        int si[4] = {si4.x, si4.y, si4.z, si4.w};

        int    cur = -1, cnt = 0;
        float4 sum = make_float4(0.f, 0.f, 0.f, 0.f);

        #pragma unroll
        for (int jo = 0; jo < 32; jo += 8) {
            float4 val[8];
            #pragma unroll
            for (int jj = 0; jj < 8; ++jj) {
                const int j = jo + jj;
                int idx = __shfl_sync(FULL_MASK, gi[j & 3], j >> 2, 8);
                val[jj] = __ldg((const float4*)(src + (long long)idx * D) + sub);
            }
            #pragma unroll
            for (int jj = 0; jj < 8; ++jj) {
                const int j = jo + jj;
                int seg = __shfl_sync(FULL_MASK, si[j & 3], j >> 2, 8);
                if (seg != cur) {
                    if (cnt) flush_seg(out4, cur, sum, cnt, sub);
                    cur = seg; sum = make_float4(0.f, 0.f, 0.f, 0.f); cnt = 0;
                }
                sum.x += val[jj].x; sum.y += val[jj].y;
                sum.z += val[jj].z; sum.w += val[jj].w;
                ++cnt;
            }
        }
        if (cnt) flush_seg(out4, cur, sum, cnt, sub);
    } else {
        // ---------- tail path: partial chunk, per-group scalar loop ----------
        const int group = lane >> 3;
        long long gstart = start + (long long)group * 32;
        long long gend   = min(gstart + 32, (long long)E);

        int    cur = -1, cnt = 0;
        float4 sum = make_float4(0.f, 0.f, 0.f, 0.f);

        for (long long e = gstart; e < gend; ++e) {
            int idx = __ldg(gidx + e);
            int seg = __ldg(sid  + e);
            float4 v = __ldg((const float4*)(src + (long long)idx * D) + sub);
            if (seg != cur) {
                if (cnt) flush_seg(out4, cur, sum, cnt, sub);
                cur = seg; sum = make_float4(0.f, 0.f, 0.f, 0.f); cnt = 0;
            }
            sum.x += v.x; sum.y += v.y; sum.z += v.z; sum.w += v.w;
            ++cnt;
        }
        if (cnt) flush_seg(out4, cur, sum, cnt, sub);
    }
}

// ---------------------------------------------------------------------------
// Kernel 2: out[n][:] *= 1/max(count,1); re-zero g_counts for next call.
// Pure streaming: 25.6 MB out RMW + broadcast count reads + 0.4 MB zeros.
// Empty segments: count 0 -> inv finite, sum 0 -> out 0 (matches reference).
// ---------------------------------------------------------------------------
__global__ void k_fin(float4* __restrict__ out4, int nq) {
    int i = blockIdx.x * blockDim.x + threadIdx.x;
    if (i >= nq) return;
    const int n = i >> 3;
    const float c = g_counts[n];        // 8 threads same addr -> broadcast
    const float inv = 1.0f / fmaxf(c, 1.0f);
    float4 v = out4[i];
    v.x *= inv; v.y *= inv; v.z *= inv; v.w *= inv;
    out4[i] = v;
    if ((i & 7) == 0) g_counts[n] = 0.0f;   // restore invariant for replays
}

// ---------------------------------------------------------------------------
extern "C" void kernel_launch(void* const* d_in, const int* in_sizes, int n_in,
                              void* d_out, int out_size)
{
    const float* src  = (const float*)d_in[0];   // [N, 32] f32
    const int*   gidx = (const int*)  d_in[1];   // [E] i32
    const int*   sid  = (const int*)  d_in[2];   // [E] i32 (sorted)
    float4*      out4 = (float4*)d_out;          // [N, 32] f32

    const int E  = in_sizes[1];
    const int nq = out_size / 4;

    // 0) zero the output accumulator (graph memset node)
    cudaMemsetAsync(d_out, 0, (size_t)out_size * sizeof(float), 0);

    // 1) gather + raw segment sums + counts
    {
        long long warps  = ((long long)E + EPW - 1) / EPW;
        long long tcount = warps * 32;
        int blocks = (int)((tcount + 255) / 256);
        k_agg<<<blocks, 256>>>(src, gidx, sid, out4, E);
    }
    // 2) divide by counts, restore count zeros
    {
        int blocks = (nq + 255) / 256;
        k_fin<<<blocks, 256>>>(out4, nq);
    }
}